// round 15
// baseline (speedup 1.0000x reference)
#include <cuda_runtime.h>
#include <math.h>

#define NBATCH 2048

// ---- image layout: plain rows, stride 68 (=17 float4), x stored at idx x+2 ----
// row ry = y+2 (0..66, rows 0,1,66 zero), idx 0,1,66,67 zero pad
#define IMROW 68
#define IMCH  (67 * IMROW)          // 4556; /4 = 1139 float4 words
#define S_W1  13668                 // conv1 weights [c][ky][f][12] = 3960 (float4-aligned)
#define SMEM_FLOATS (S_W1 + 3960)   // 17628 floats = 70512 B; occ 2 by regs anyway

// aliases in the image region (dead after conv1 mainloop):
#define S_TMP1 0                    // q1 partials / later q2+q3 sums [10][15][16] = 2400
#define S_TMP2 2400                 // q3 partials [10][15][16] = 2400
#define S_C1   4800                 // conv1 out [10][15][16] = 2400
#define S_W2P  7200                 // conv2 weights padded [16][10][5][8] = 6400 (ends 13600)
#define S_P1P  13600                // pool1 zero-padded [10][11][12] = 1320 (overlaps dead W1)
#define S_C2   14920                // conv2 out [16][4][4] = 256
#define S_FL   15176                // flat 64 (ends 15240 < 17628)

__device__ __forceinline__ float leaky(float v) { return v > 0.f ? v : 0.01f * v; }

// one (c,ky) range of conv1 rows: 5 filters (fh half) x 8 adjacent pixels (group g)
__device__ __forceinline__ void c1_rows(const float* __restrict__ sm,
                                        int c, int ky0, int ky1,
                                        int oy, int g, int fh,
                                        float acc[5][8])
{
    const float4* rp = (const float4*)sm + c * (IMCH / 4) + (4 * oy) * 17 + 8 * g;
    const float*  wb = sm + S_W1 + (c * 11) * 120 + fh * 60;
    #pragma unroll 1
    for (int ky = ky0; ky < ky1; ky++) {
        float4 X[10];
        const float4* row = rp + ky * 17;
        #pragma unroll
        for (int j = 0; j < 10; j++) X[j] = row[j];
        const float* xs = (const float*)X;          // pixel d taps = xs[4d+k]
        const float* wr = wb + ky * 120;
        #pragma unroll
        for (int f = 0; f < 5; f++) {
            float4 wa = *(const float4*)(wr + f * 12);
            float4 wv = *(const float4*)(wr + f * 12 + 4);
            float4 wc = *(const float4*)(wr + f * 12 + 8);
            float w[11] = {wa.x, wa.y, wa.z, wa.w,
                           wv.x, wv.y, wv.z, wv.w,
                           wc.x, wc.y, wc.z};
            #pragma unroll
            for (int d = 0; d < 8; d++) {
                float a = acc[f][d];
                #pragma unroll
                for (int k = 0; k < 11; k++)
                    a = fmaf(xs[4 * d + k], w[k], a);
                acc[f][d] = a;
            }
        }
    }
}

__global__ void __launch_bounds__(256, 2)
cnn_kernel(const float* __restrict__ im,
           const float* __restrict__ w1,
           const float* __restrict__ w2,
           const float* __restrict__ b2,
           const float* __restrict__ lw,
           const float* __restrict__ lb,
           float* __restrict__ out)
{
    extern __shared__ float sm[];
    const int b   = blockIdx.x;
    const int tid = threadIdx.x;

    // ---- zero image region (halo correctness), then scatter ----
    for (int i = tid; i < 3 * IMCH; i += 256) sm[i] = 0.f;
    __syncthreads();

    {
        const float2* gim = (const float2*)(im + (size_t)b * 12288);
        for (int i = tid; i < 6144; i += 256) {
            float2 v = gim[i];
            int fi = i << 1;
            int c  = fi >> 12;
            int y  = (fi & 4095) >> 6;
            int x  = fi & 63;
            int base = c * IMCH + (y + 2) * IMROW + x + 2;
            sm[base]     = v.x;
            sm[base + 1] = v.y;
        }
    }
    // conv1 weights: [f][c][ky][kx] -> [c][ky][f][12] (pad float wc.w never used)
    for (int i = tid; i < 3630; i += 256) {
        int f   = i / 363;
        int rem = i % 363;
        int c   = rem / 121;
        int r2  = rem % 121;
        int ky  = r2 / 11;
        int kx  = r2 % 11;
        sm[S_W1 + ((c * 11 + ky) * 10 + f) * 12 + kx] = w1[i];
    }

    // graph half is analytically constant: softmax == 0.05 (verified exact R1-R14)
    if (tid < 20)
        out[b * 20 + tid] = 0.05f;

    __syncthreads();

    // ---- conv1 (11x11, s4, p2): 15x15 out, 10 filters ----
    // 4-way K-split over rows m = c*11+ky (0..32): q = tid>>6
    //   q0: c0 ky0-7 | q1: c0 ky8-10 + c1 ky0-4 | q2: c1 ky5-10 + c2 ky0-1 | q3: c2 ky2-10
    // within quarter (a = tid&63, active a<60): fh = a&1, g = (a>>1)&1, oy = a>>2
    //   pixels ox = 8g..8g+7 (ox=15 garbage, lands in unused C1 pad col)
    const int  q  = tid >> 6;
    const int  a  = tid & 63;
    const bool c1act = (a < 60);
    const int  fh = a & 1, g = (a >> 1) & 1, oy = a >> 2;

    float acc[5][8];
    #pragma unroll
    for (int f = 0; f < 5; f++)
        #pragma unroll
        for (int d = 0; d < 8; d++) acc[f][d] = 0.f;

    if (c1act) {
        if      (q == 0)  c1_rows(sm, 0, 0, 8,  oy, g, fh, acc);
        else if (q == 1) { c1_rows(sm, 0, 8, 11, oy, g, fh, acc);
                           c1_rows(sm, 1, 0, 5,  oy, g, fh, acc); }
        else if (q == 2) { c1_rows(sm, 1, 5, 11, oy, g, fh, acc);
                           c1_rows(sm, 2, 0, 2,  oy, g, fh, acc); }
        else             { c1_rows(sm, 2, 2, 11, oy, g, fh, acc); }
    }
    __syncthreads();   // image + w1 reads done; whole region reusable

    // window A: q1 -> TMP1, q3 -> TMP2 (raw partials); stage W2P; zero P1P
    if (c1act && (q == 1 || q == 3)) {
        const int base = (q == 1) ? S_TMP1 : S_TMP2;
        #pragma unroll
        for (int f = 0; f < 5; f++) {
            const int fg = fh * 5 + f;
            float* p = &sm[base + (fg * 15 + oy) * 16 + 8 * g];
            *(float4*)p       = make_float4(acc[f][0], acc[f][1], acc[f][2], acc[f][3]);
            *(float4*)(p + 4) = make_float4(acc[f][4], acc[f][5], acc[f][6], acc[f][7]);
        }
    }
    for (int i = tid; i < 4000; i += 256) {       // conv2 weights padded [f][c][ky][8]
        int kx = i % 5; int t = i / 5;
        int ky = t % 5; t /= 5;
        int c  = t % 10; int f = t / 10;
        sm[S_W2P + (((f * 10 + c) * 5) + ky) * 8 + kx] = w2[i];
    }
    for (int i = tid; i < 1320; i += 256)         // zero-fill padded pool1
        sm[S_P1P + i] = 0.f;
    __syncthreads();

    // window B: q0 += TMP1 ; q2 += TMP2 then write back to TMP2 (in-place, own addr)
    if (c1act && q == 0) {
        #pragma unroll
        for (int f = 0; f < 5; f++) {
            const int fg = fh * 5 + f;
            const float* p = &sm[S_TMP1 + (fg * 15 + oy) * 16 + 8 * g];
            #pragma unroll
            for (int d = 0; d < 8; d++) acc[f][d] += p[d];
        }
    }
    if (c1act && q == 2) {
        #pragma unroll
        for (int f = 0; f < 5; f++) {
            const int fg = fh * 5 + f;
            float* p = &sm[S_TMP2 + (fg * 15 + oy) * 16 + 8 * g];
            float4 r0 = make_float4(acc[f][0] + p[0], acc[f][1] + p[1],
                                    acc[f][2] + p[2], acc[f][3] + p[3]);
            float4 r1 = make_float4(acc[f][4] + p[4], acc[f][5] + p[5],
                                    acc[f][6] + p[6], acc[f][7] + p[7]);
            *(float4*)p       = r0;
            *(float4*)(p + 4) = r1;
        }
    }
    __syncthreads();

    // window C: q0 folds q2+q3 sums, leaky -> C1 (col 15 pad never read by pool)
    if (c1act && q == 0) {
        #pragma unroll
        for (int f = 0; f < 5; f++) {
            const int fg = fh * 5 + f;
            const float* p = &sm[S_TMP2 + (fg * 15 + oy) * 16 + 8 * g];
            float* cp = &sm[S_C1 + (fg * 15 + oy) * 16 + 8 * g];
            *(float4*)cp = make_float4(leaky(acc[f][0] + p[0]), leaky(acc[f][1] + p[1]),
                                       leaky(acc[f][2] + p[2]), leaky(acc[f][3] + p[3]));
            *(float4*)(cp + 4) = make_float4(leaky(acc[f][4] + p[4]), leaky(acc[f][5] + p[5]),
                                             leaky(acc[f][6] + p[6]), leaky(acc[f][7] + p[7]));
        }
    }
    __syncthreads();

    // ---- maxpool 3x3 s2: 15x15 -> 7x7, write into zero-padded [10][11][12] ----
    for (int i = tid; i < 490; i += 256) {
        int f = i / 49, r = i % 49;
        int py = r / 7, px = r % 7;
        float m = -1e30f;
        #pragma unroll
        for (int dy = 0; dy < 3; dy++)
            #pragma unroll
            for (int dx = 0; dx < 3; dx++)
                m = fmaxf(m, sm[S_C1 + (f * 15 + (2 * py + dy)) * 16 + (2 * px + dx)]);
        sm[S_P1P + (f * 11 + py + 2) * 12 + px + 2] = m;
    }
    __syncthreads();

    // ---- conv2 (5x5, s2, p2): 7x7 -> 4x4, 10 -> 16 ch, guard-free ----
    {
        int f   = tid >> 4;
        int r   = tid & 15;
        int oy2 = r >> 2;
        int ox2 = r & 3;
        float av = b2[f];
        #pragma unroll 1
        for (int c = 0; c < 10; c++) {
            #pragma unroll
            for (int ky = 0; ky < 5; ky++) {
                const float* prow = &sm[S_P1P + (c * 11 + 2 * oy2 + ky) * 12 + 2 * ox2];
                const float4 wv = *(const float4*)&sm[S_W2P + ((f * 10 + c) * 5 + ky) * 8];
                const float  w4 = sm[S_W2P + ((f * 10 + c) * 5 + ky) * 8 + 4];
                av = fmaf(prow[0], wv.x, av);
                av = fmaf(prow[1], wv.y, av);
                av = fmaf(prow[2], wv.z, av);
                av = fmaf(prow[3], wv.w, av);
                av = fmaf(prow[4], w4,  av);
            }
        }
        sm[S_C2 + f * 16 + oy2 * 4 + ox2] = leaky(av);
    }
    __syncthreads();

    // ---- maxpool 2x2 s2: 4x4 -> 2x2, flatten ----
    if (tid < 64) {
        int f = tid >> 2, py = (tid >> 1) & 1, px = tid & 1;
        float m = sm[S_C2 + f * 16 + (2 * py) * 4 + (2 * px)];
        m = fmaxf(m, sm[S_C2 + f * 16 + (2 * py) * 4 + (2 * px + 1)]);
        m = fmaxf(m, sm[S_C2 + f * 16 + (2 * py + 1) * 4 + (2 * px)]);
        m = fmaxf(m, sm[S_C2 + f * 16 + (2 * py + 1) * 4 + (2 * px + 1)]);
        sm[S_FL + tid] = m;   // flat index == tid
    }
    __syncthreads();

    // ---- linear 64 -> 2 + sigmoid ----
    if (tid < 2) {
        float a2 = lb[tid];
        #pragma unroll
        for (int k = 0; k < 64; k++)
            a2 = fmaf(sm[S_FL + k], lw[tid * 64 + k], a2);
        out[NBATCH * 20 + b * 2 + tid] = 1.f / (1.f + __expf(-a2));
    }
}

extern "C" void kernel_launch(void* const* d_in, const int* in_sizes, int n_in,
                              void* d_out, int out_size)
{
    (void)in_sizes; (void)n_in; (void)out_size;
    const float* im = (const float*)d_in[0];
    // d_in[1] = x, d_in[2] = edge_index : dead (graph output is constant 0.05)
    const float* w1 = (const float*)d_in[3];
    const float* w2 = (const float*)d_in[4];
    const float* b2 = (const float*)d_in[5];
    const float* lw = (const float*)d_in[6];
    const float* lb = (const float*)d_in[7];
    float* out = (float*)d_out;

    cudaFuncSetAttribute(cnn_kernel, cudaFuncAttributeMaxDynamicSharedMemorySize,
                         SMEM_FLOATS * sizeof(float));
    cnn_kernel<<<NBATCH, 256, SMEM_FLOATS * sizeof(float)>>>(im, w1, w2, b2, lw, lb, out);
}

// round 16
// speedup vs baseline: 1.2245x; 1.2245x over previous
#include <cuda_runtime.h>
#include <math.h>

#define NBATCH 2048

// ---- image layout: plain rows, stride 68 (=17 float4), x stored at idx x+2 ----
// row ry = y+2 (0..66; rows 0,1,66 zero), cols 0,1,66,67 zero
#define IMROW 68
#define IMCH  (67 * IMROW)          // 4556 (even; /4 = 1139 words)
#define S_W1  13668                 // conv1 weights [c][ky][f][12] = 3960 (float4-aligned)
#define SMEM_FLOATS (S_W1 + 3960)   // 17628 floats = 70512 bytes -> 3 CTAs/SM

// aliases in the image region (dead after conv1 mainloop):
#define S_TMP  0                    // group-B partials [10][15][16] = 2400
#define S_C1   2400                 // conv1 out [10][15][16] = 2400
#define S_W2Q  4800                 // conv2 weights, f-stride 404: 15*404+400 = 6460 (ends 11260)
#define S_P1P  11264                // pool1 zero-padded [10][11][12] = 1320 (ends 12584)
#define S_C2   12584                // conv2 out [16][4][4] = 256
#define S_FL   12840                // flat 64 (ends 12904 < 13668 ✓)

__device__ __forceinline__ float leaky(float v) { return v > 0.f ? v : 0.01f * v; }

// one (c,ky) reduction row of conv1 for 5 filters x 4 adjacent pixels (R11/R14-proven)
__device__ __forceinline__ void c1_row(const float* __restrict__ sm,
                                       int c, int ky, int oy, int pr, int fh,
                                       float acc[5][4])
{
    const float4* row = (const float4*)&sm[c * IMCH + (4 * oy + ky) * IMROW] + 4 * pr;
    float4 X[6];
    #pragma unroll
    for (int j = 0; j < 6; j++) X[j] = row[j];
    const float* xs = (const float*)X;   // pixel d taps = xs[4d+k], k=0..10
    const float* wr = &sm[S_W1 + (c * 11 + ky) * 120 + fh * 60];
    #pragma unroll
    for (int f = 0; f < 5; f++) {
        float4 wa = *(const float4*)(wr + f * 12);
        float4 wb = *(const float4*)(wr + f * 12 + 4);
        float4 wc = *(const float4*)(wr + f * 12 + 8);
        float w[11] = {wa.x, wa.y, wa.z, wa.w,
                       wb.x, wb.y, wb.z, wb.w,
                       wc.x, wc.y, wc.z};
        #pragma unroll
        for (int d = 0; d < 4; d++) {
            float a = acc[f][d];
            #pragma unroll
            for (int k = 0; k < 11; k++)
                a = fmaf(xs[4 * d + k], w[k], a);
            acc[f][d] = a;
        }
    }
}

__global__ void __launch_bounds__(256, 3)
cnn_kernel(const float* __restrict__ im,
           const float* __restrict__ w1,
           const float* __restrict__ w2,
           const float* __restrict__ b2,
           const float* __restrict__ lw,
           const float* __restrict__ lb,
           float* __restrict__ out)
{
    extern __shared__ float sm[];
    const int b   = blockIdx.x;
    const int tid = threadIdx.x;

    // ---- halo-only zeroing (rows 0,1,66; cols 0,1,66,67; W1 pad lanes) ----
    for (int i = tid; i < 612; i += 256) {          // halo rows: 3ch x 3rows x 68
        int ch = i / 204, r = i % 204;
        int rr = r / 68;
        int ry = (rr == 2) ? 66 : rr;
        sm[ch * IMCH + ry * IMROW + (r % 68)] = 0.f;
    }
    for (int i = tid; i < 768; i += 256) {          // halo cols: 3ch x 64rows x 4
        int ch = i >> 8, r = i & 255;
        int ry = (r >> 2) + 2;
        int s  = r & 3;
        int col = (s < 2) ? s : (64 + s);           // 0,1,66,67
        sm[ch * IMCH + ry * IMROW + col] = 0.f;
    }
    for (int i = tid; i < 3960; i += 256)           // W1 region (covers kx=11 pad lane)
        sm[S_W1 + i] = 0.f;
    __syncthreads();

    // ---- stage image (float2 stores: x even -> base even) + conv1 weights ----
    {
        const float2* gim = (const float2*)(im + (size_t)b * 12288);
        for (int i = tid; i < 6144; i += 256) {
            float2 v = gim[i];
            int fi = i << 1;
            int c  = fi >> 12;
            int y  = (fi & 4095) >> 6;
            int x  = fi & 63;
            *(float2*)&sm[c * IMCH + (y + 2) * IMROW + x + 2] = v;
        }
    }
    // conv1 weights: [f][c][ky][kx] -> [c][ky][f][12]
    for (int i = tid; i < 3630; i += 256) {
        int f   = i / 363;
        int rem = i % 363;
        int c   = rem / 121;
        int r2  = rem % 121;
        int ky  = r2 / 11;
        int kx  = r2 % 11;
        sm[S_W1 + ((c * 11 + ky) * 10 + f) * 12 + kx] = w1[i];
    }

    // graph half is analytically constant: softmax == 0.05 (verified exact R1-R15)
    if (tid < 20)
        out[b * 20 + tid] = 0.05f;

    __syncthreads();

    // ---- conv1 (11x11, s4, p2): 15x15 out, K-split across warp halves (R14) ----
    // group A = warps 0-3 (tid<120 active): rows c0 ky0-10, c1 ky0-4
    // group B = warps 4-7 (tid-128<120):    rows c1 ky5-10, c2 ky0-10
    // within group: oy = a>>3, pr = (a>>1)&3, fh = a&1; pixels ox = 4pr+d
    const bool grpB = (tid >= 128);
    const int  a    = grpB ? (tid - 128) : tid;
    const bool c1act = (a < 120);
    const int  oy = a >> 3, pr = (a >> 1) & 3, fh = a & 1;

    float acc[5][4];
    #pragma unroll
    for (int f = 0; f < 5; f++)
        #pragma unroll
        for (int d = 0; d < 4; d++) acc[f][d] = 0.f;

    if (c1act) {
        if (!grpB) {
            #pragma unroll 1
            for (int ky = 0; ky < 11; ky++) c1_row(sm, 0, ky, oy, pr, fh, acc);
            #pragma unroll 1
            for (int ky = 0; ky < 5;  ky++) c1_row(sm, 1, ky, oy, pr, fh, acc);
        } else {
            #pragma unroll 1
            for (int ky = 5; ky < 11; ky++) c1_row(sm, 1, ky, oy, pr, fh, acc);
            #pragma unroll 1
            for (int ky = 0; ky < 11; ky++) c1_row(sm, 2, ky, oy, pr, fh, acc);
        }
    }
    __syncthreads();   // image + w1 reads done; both regions reusable

    // window A: group B parks raw partials; stage conv2 weights; zero pool1 pad
    if (grpB && c1act) {
        #pragma unroll
        for (int f = 0; f < 5; f++) {
            const int fg = fh * 5 + f;
            *(float4*)&sm[S_TMP + (fg * 15 + oy) * 16 + 4 * pr] =
                make_float4(acc[f][0], acc[f][1], acc[f][2], acc[f][3]);
        }
    }
    for (int i = tid; i < 4000; i += 256) {   // conv2 weights: [f][c][ky][kx] -> f*404 + (c*5+ky)*8 + kx
        int kx = i % 5; int t = i / 5;
        int ky = t % 5; t /= 5;
        int c  = t % 10; int f = t / 10;
        sm[S_W2Q + f * 404 + (c * 5 + ky) * 8 + kx] = w2[i];
    }
    for (int i = tid; i < 1320; i += 256)     // zero-fill padded pool1 [10][11][12]
        sm[S_P1P + i] = 0.f;
    __syncthreads();

    // window B: group A combines + leaky -> C1 (col 15 pad never read by pool)
    if (!grpB && c1act) {
        #pragma unroll
        for (int f = 0; f < 5; f++) {
            const int fg = fh * 5 + f;
            float4 p = *(const float4*)&sm[S_TMP + (fg * 15 + oy) * 16 + 4 * pr];
            *(float4*)&sm[S_C1 + (fg * 15 + oy) * 16 + 4 * pr] =
                make_float4(leaky(acc[f][0] + p.x), leaky(acc[f][1] + p.y),
                            leaky(acc[f][2] + p.z), leaky(acc[f][3] + p.w));
        }
    }
    __syncthreads();

    // ---- maxpool 3x3 s2: 15x15 -> 7x7 into zero-padded [10][11][12] ----
    for (int i = tid; i < 490; i += 256) {
        int f = i / 49, r = i % 49;
        int py = r / 7, px = r % 7;
        float m = -1e30f;
        #pragma unroll
        for (int dy = 0; dy < 3; dy++)
            #pragma unroll
            for (int dx = 0; dx < 3; dx++)
                m = fmaxf(m, sm[S_C1 + (f * 15 + (2 * py + dy)) * 16 + (2 * px + dx)]);
        sm[S_P1P + (f * 11 + py + 2) * 12 + px + 2] = m;
    }
    __syncthreads();

    // ---- conv2 (5x5, s2, p2): 7x7 -> 4x4, 10 -> 16 ch ----
    // 64 threads = lanes 0-15 of warps 0,2,4,6 (one warp per SMSP, oy2 = warp)
    // thread = (f, oy2), 4 pixels ox2=0..3: weights amortized x4, inputs = whole
    // padded row (3 float4 broadcasts); pixel ox2 tap kx = row float [2*ox2+kx].
    if ((tid & 48) == 0) {
        const int t   = ((tid >> 6) << 4) | (tid & 15);  // 0..63
        const int f   = t & 15;
        const int oy2 = t >> 4;
        float av0 = b2[f], av1 = av0, av2 = av0, av3 = av0;
        #pragma unroll 1
        for (int c = 0; c < 10; c++) {
            #pragma unroll
            for (int ky = 0; ky < 5; ky++) {
                const float* prow = &sm[S_P1P + (c * 11 + 2 * oy2 + ky) * 12];
                float4 A = *(const float4*)prow;
                float4 B4 = *(const float4*)(prow + 4);
                float4 C4 = *(const float4*)(prow + 8);
                float r[12] = {A.x, A.y, A.z, A.w, B4.x, B4.y, B4.z, B4.w,
                               C4.x, C4.y, C4.z, C4.w};
                const float* wp = &sm[S_W2Q + f * 404 + (c * 5 + ky) * 8];
                float4 W = *(const float4*)wp;
                float  w4 = wp[4];
                float w[5] = {W.x, W.y, W.z, W.w, w4};
                #pragma unroll
                for (int kx = 0; kx < 5; kx++) {
                    av0 = fmaf(r[0 + kx], w[kx], av0);
                    av1 = fmaf(r[2 + kx], w[kx], av1);
                    av2 = fmaf(r[4 + kx], w[kx], av2);
                    av3 = fmaf(r[6 + kx], w[kx], av3);
                }
            }
        }
        *(float4*)&sm[S_C2 + f * 16 + oy2 * 4] =
            make_float4(leaky(av0), leaky(av1), leaky(av2), leaky(av3));
    }
    __syncthreads();

    // ---- maxpool 2x2 s2: 4x4 -> 2x2, flatten ----
    if (tid < 64) {
        int f = tid >> 2, py = (tid >> 1) & 1, px = tid & 1;
        float m = sm[S_C2 + f * 16 + (2 * py) * 4 + (2 * px)];
        m = fmaxf(m, sm[S_C2 + f * 16 + (2 * py) * 4 + (2 * px + 1)]);
        m = fmaxf(m, sm[S_C2 + f * 16 + (2 * py + 1) * 4 + (2 * px)]);
        m = fmaxf(m, sm[S_C2 + f * 16 + (2 * py + 1) * 4 + (2 * px + 1)]);
        sm[S_FL + tid] = m;   // flat index == tid
    }
    __syncthreads();

    // ---- linear 64 -> 2 + sigmoid ----
    if (tid < 2) {
        float a2 = lb[tid];
        #pragma unroll
        for (int k = 0; k < 64; k++)
            a2 = fmaf(sm[S_FL + k], lw[tid * 64 + k], a2);
        out[NBATCH * 20 + b * 2 + tid] = 1.f / (1.f + __expf(-a2));
    }
}

extern "C" void kernel_launch(void* const* d_in, const int* in_sizes, int n_in,
                              void* d_out, int out_size)
{
    (void)in_sizes; (void)n_in; (void)out_size;
    const float* im = (const float*)d_in[0];
    // d_in[1] = x, d_in[2] = edge_index : dead (graph output is constant 0.05)
    const float* w1 = (const float*)d_in[3];
    const float* w2 = (const float*)d_in[4];
    const float* b2 = (const float*)d_in[5];
    const float* lw = (const float*)d_in[6];
    const float* lb = (const float*)d_in[7];
    float* out = (float*)d_out;

    cudaFuncSetAttribute(cnn_kernel, cudaFuncAttributeMaxDynamicSharedMemorySize,
                         SMEM_FLOATS * sizeof(float));
    cnn_kernel<<<NBATCH, 256, SMEM_FLOATS * sizeof(float)>>>(im, w1, w2, b2, lw, lb, out);
}